// round 10
// baseline (speedup 1.0000x reference)
#include <cuda_runtime.h>
#include <math.h>

#define HH 512
#define WW 512
#define NB 8
#define NIMG 16
#define NBLK 128         // 8 pairs x 16 row-chunks
#define NTHR 512
#define NWARP 16
#define CHROWS 32        // central rows per block (per image)
#define HALO 3
#define LROWS 38         // CHROWS + 2*HALO
#define FULL 0xffffffffu

// packed masks (fallback path only): [image][row][16 words] = 512 KB
__device__ unsigned int g_mbits[NIMG][HH][16];
// per-(image, chunk) nonempty flags (overwritten every replay)
__device__ int g_anyp[NIMG][16];
// running max dt^2 per EDT-image; reset by finalizer each replay
__device__ unsigned int g_hmax[NIMG];
// monotonic counters (grow across replays)
__device__ unsigned int g_ph1 = 0;
__device__ unsigned int g_done = 0;

// nearest set-bit horizontal distance in a 512-bit packed row (clamped 1024)
__device__ __forceinline__ int nearest_dj(const unsigned int* __restrict__ rb, int j) {
    int jw = j >> 5, jb = j & 31;
    unsigned wj = rb[jw];
    int dright = 1 << 20;
    unsigned hi = wj >> jb;
    if (hi) dright = __ffs(hi) - 1;
    else {
        #pragma unroll 4
        for (int w = jw + 1; w < 16; w++) {
            unsigned x = rb[w];
            if (x) { dright = (w << 5) + __ffs(x) - 1 - j; break; }
        }
    }
    int dleft = 1 << 20;
    unsigned lo = jb ? (wj & ((1u << jb) - 1u)) : 0u;
    if (lo) dleft = jb - (31 - __clz(lo));
    else {
        #pragma unroll 4
        for (int w = jw - 1; w >= 0; w--) {
            if ((j - ((w << 5) + 31)) >= dright) break;
            unsigned x = rb[w];
            if (x) { dleft = j - ((w << 5) + 31 - __clz(x)); break; }
        }
    }
    return min(min(dright, dleft), 1024);
}

// exact squared distance for an (ultra-rare) pixel with empty 7x7
__device__ __noinline__ int exact_d2(int im, int row, int j) {
    int best2 = 1 << 19;
    for (int dr = 0; dr < HH; dr++) {
        int dr2 = dr * dr;
        if (dr2 >= best2) break;
        int r = row - dr;
        if (r >= 0) {
            int dj = nearest_dj(g_mbits[im][r], j);
            best2 = min(best2, dr2 + dj * dj);
        }
        if (dr) {
            r = row + dr;
            if (r < HH) {
                int dj = nearest_dj(g_mbits[im][r], j);
                best2 = min(best2, dr2 + dj * dj);
            }
        }
    }
    return best2;
}

__device__ __forceinline__ unsigned nib4(float4 v) {
    return (v.x > 0.5f ? 1u : 0u) | (v.y > 0.5f ? 2u : 0u)
         | (v.z > 0.5f ? 4u : 0u) | (v.w > 0.5f ? 8u : 0u);
}
__device__ __forceinline__ unsigned sh1(unsigned x, unsigned xm, unsigned xp) {
    return ((x << 1) | (xm >> 31)) | ((x >> 1) | (xp << 31));
}
__device__ __forceinline__ unsigned sh2(unsigned x, unsigned xm, unsigned xp) {
    return ((x << 2) | (xm >> 30)) | ((x >> 2) | (xp << 30));
}
__device__ __forceinline__ unsigned sh3(unsigned x, unsigned xm, unsigned xp) {
    return ((x << 3) | (xm >> 29)) | ((x >> 3) | (xp << 29));
}

// radius-3 exact tier classification for one direction.
// Returns max d^2 in {0..18} over gated pixels; *leftover = gated pixels with empty 7x7.
__device__ __forceinline__ int tiers(unsigned C, unsigned U1, unsigned U2, unsigned U3,
                                     unsigned D1, unsigned D2, unsigned D3,
                                     unsigned G, int lane, int wj, unsigned* leftover) {
    unsigned Cm  = __shfl_sync(FULL, C,  (lane + 31) & 31);
    unsigned Cp  = __shfl_sync(FULL, C,  (lane + 1) & 31);
    unsigned U1m = __shfl_sync(FULL, U1, (lane + 31) & 31);
    unsigned U1p = __shfl_sync(FULL, U1, (lane + 1) & 31);
    unsigned U2m = __shfl_sync(FULL, U2, (lane + 31) & 31);
    unsigned U2p = __shfl_sync(FULL, U2, (lane + 1) & 31);
    unsigned U3m = __shfl_sync(FULL, U3, (lane + 31) & 31);
    unsigned U3p = __shfl_sync(FULL, U3, (lane + 1) & 31);
    unsigned D1m = __shfl_sync(FULL, D1, (lane + 31) & 31);
    unsigned D1p = __shfl_sync(FULL, D1, (lane + 1) & 31);
    unsigned D2m = __shfl_sync(FULL, D2, (lane + 31) & 31);
    unsigned D2p = __shfl_sync(FULL, D2, (lane + 1) & 31);
    unsigned D3m = __shfl_sync(FULL, D3, (lane + 31) & 31);
    unsigned D3p = __shfl_sync(FULL, D3, (lane + 1) & 31);
    if (wj == 0)  { Cm = 0u; U1m = 0u; U2m = 0u; U3m = 0u; D1m = 0u; D2m = 0u; D3m = 0u; }
    if (wj == 15) { Cp = 0u; U1p = 0u; U2p = 0u; U3p = 0u; D1p = 0u; D2p = 0u; D3p = 0u; }

    unsigned t1  = sh1(C, Cm, Cp) | U1 | D1;
    unsigned t2  = sh1(U1, U1m, U1p) | sh1(D1, D1m, D1p);
    unsigned t4  = sh2(C, Cm, Cp) | U2 | D2;
    unsigned t5  = sh2(U1, U1m, U1p) | sh2(D1, D1m, D1p)
                 | sh1(U2, U2m, U2p) | sh1(D2, D2m, D2p);
    unsigned t8  = sh2(U2, U2m, U2p) | sh2(D2, D2m, D2p);
    unsigned t9  = sh3(C, Cm, Cp) | U3 | D3;
    unsigned t10 = sh3(U1, U1m, U1p) | sh3(D1, D1m, D1p)
                 | sh1(U3, U3m, U3p) | sh1(D3, D3m, D3p);
    unsigned t13 = sh3(U2, U2m, U2p) | sh3(D2, D2m, D2p)
                 | sh2(U3, U3m, U3p) | sh2(D3, D3m, D3p);
    unsigned t18 = sh3(U3, U3m, U3p) | sh3(D3, D3m, D3p);

    unsigned n = C;
    int v = 0;
    if (G & t1  & ~n) v = 1;  n |= t1;
    if (G & t2  & ~n) v = 2;  n |= t2;
    if (G & t4  & ~n) v = 4;  n |= t4;
    if (G & t5  & ~n) v = 5;  n |= t5;
    if (G & t8  & ~n) v = 8;  n |= t8;
    if (G & t9  & ~n) v = 9;  n |= t9;
    if (G & t10 & ~n) v = 10; n |= t10;
    if (G & t13 & ~n) v = 13; n |= t13;
    if (G & t18 & ~n) v = 18; n |= t18;
    *leftover = G & ~n;
    return v;
}

__global__ __launch_bounds__(NTHR)
void hausdorff_fused(const float* __restrict__ inA,
                     const float* __restrict__ inB,
                     float* __restrict__ out) {
    __shared__ unsigned s_mask[2][LROWS][17];      // [img][local row][word]
    __shared__ __align__(8) unsigned char s_nib[NWARP][128];
    __shared__ int s_redA[NWARP], s_redB[NWARP];
    __shared__ unsigned s_ph1tgt, s_old;

    const int t    = threadIdx.x;
    const int w    = t >> 5;
    const int lane = t & 31;
    const int blk  = blockIdx.x;
    const int pr    = blk >> 4;         // pair 0..7
    const int chunk = blk & 15;         // row chunk 0..15
    const int r0abs = chunk * CHROWS;
    const int half  = lane >> 4;
    const int wj    = lane & 15;
    const float* srcA = inA + (size_t)pr * HH * WW;
    const float* srcB = inB + (size_t)pr * HH * WW;

    // ------- Phase A: load band+halo of BOTH images, pack into smem ---------
    unsigned accA = 0u, accB = 0u;
    #pragma unroll
    for (int it = 0; it < 3; it++) {
        int p = it * NWARP + w;               // row-pair index, 0..39
        if (p < 38) {
            int img = (p >= 19) ? 1 : 0;
            int rl  = 2 * p - img * 38;       // local row of half 0 (0..36 even)
            int abs0 = r0abs - HALO + rl;
            const float* base = img ? srcB : srcA;
            bool v0 = ((unsigned)abs0 < (unsigned)HH);
            bool v1 = ((unsigned)(abs0 + 1) < (unsigned)HH);
            float4 z = make_float4(0.f, 0.f, 0.f, 0.f);
            const float4* p0 = (const float4*)(base + (ptrdiff_t)abs0 * WW);
            const float4* p1 = (const float4*)(base + (ptrdiff_t)(abs0 + 1) * WW);
            float4 a0 = v0 ? p0[lane] : z, a1 = v0 ? p0[lane + 32] : z;
            float4 a2 = v0 ? p0[lane + 64] : z, a3 = v0 ? p0[lane + 96] : z;
            float4 b0 = v1 ? p1[lane] : z, b1 = v1 ? p1[lane + 32] : z;
            float4 b2 = v1 ? p1[lane + 64] : z, b3 = v1 ? p1[lane + 96] : z;

            unsigned char* sn = &s_nib[w][0];
            sn[0 * 32 + lane] = (unsigned char)(nib4(a0) | (nib4(b0) << 4));
            sn[1 * 32 + lane] = (unsigned char)(nib4(a1) | (nib4(b1) << 4));
            sn[2 * 32 + lane] = (unsigned char)(nib4(a2) | (nib4(b2) << 4));
            sn[3 * 32 + lane] = (unsigned char)(nib4(a3) | (nib4(b3) << 4));
            __syncwarp();
            uint2 vv = *(const uint2*)&sn[(wj >> 2) * 32 + (wj & 3) * 8];
            unsigned x = (vv.x >> (4 * half)) & 0x0F0F0F0Fu;
            unsigned y = (vv.y >> (4 * half)) & 0x0F0F0F0Fu;
            x = (x | (x >> 4)) & 0x00FF00FFu;  x = (x | (x >> 8)) & 0x0000FFFFu;
            y = (y | (y >> 4)) & 0x00FF00FFu;  y = (y | (y >> 8)) & 0x0000FFFFu;
            unsigned C = x | (y << 16);
            __syncwarp();

            int rr = rl + half;                       // local row this lane owns
            s_mask[img][rr][wj] = C;
            if (rr >= HALO && rr < HALO + CHROWS) {   // central band
                int im = img ? (pr + 8) : pr;
                g_mbits[im][r0abs + rr - HALO][wj] = C;
                if (img) accB |= C; else accA |= C;
            }
        }
    }
    int anyA = __syncthreads_or(accA != 0u);
    int anyB = __syncthreads_or(accB != 0u);
    if (t == 0) {
        g_anyp[pr][chunk]     = anyA;
        g_anyp[pr + 8][chunk] = anyB;
    }
    __threadfence();            // all threads: make g_mbits writes visible
    __syncthreads();
    if (t == 0) s_ph1tgt = (atomicAdd(&g_ph1, 1u) / NBLK + 1u) * NBLK;
    __syncthreads();

    // ------- Phase B: both directions from smem, no inter-block wait --------
    {
        const int rb = HALO + 2 * w + half;           // local central row
        const int absrow = r0abs + 2 * w + half;
        unsigned CA  = s_mask[0][rb][wj],     CB  = s_mask[1][rb][wj];
        unsigned U1A = s_mask[0][rb - 1][wj], D1A = s_mask[0][rb + 1][wj];
        unsigned U2A = s_mask[0][rb - 2][wj], D2A = s_mask[0][rb + 2][wj];
        unsigned U3A = s_mask[0][rb - 3][wj], D3A = s_mask[0][rb + 3][wj];
        unsigned U1B = s_mask[1][rb - 1][wj], D1B = s_mask[1][rb + 1][wj];
        unsigned U2B = s_mask[1][rb - 2][wj], D2B = s_mask[1][rb + 2][wj];
        unsigned U3B = s_mask[1][rb - 3][wj], D3B = s_mask[1][rb + 3][wj];

        unsigned loA, loB;
        int vA = tiers(CA, U1A, U2A, U3A, D1A, D2A, D3A, CB, lane, wj, &loA);
        int vB = tiers(CB, U1B, U2B, U3B, D1B, D2B, D3B, CA, lane, wj, &loB);

        if (__any_sync(FULL, (loA | loB) != 0u)) {    // ultra-rare exact path
            if (lane == 0) {
                while (*(volatile unsigned int*)&g_ph1 < s_ph1tgt) { }
            }
            __syncwarp();
            __threadfence();
            int j0 = wj * 32;
            while (loA) {
                int b = __ffs(loA) - 1; loA &= loA - 1u;
                vA = max(vA, exact_d2(pr, absrow, j0 + b));
            }
            while (loB) {
                int b = __ffs(loB) - 1; loB &= loB - 1u;
                vB = max(vB, exact_d2(pr + 8, absrow, j0 + b));
            }
        }

        #pragma unroll
        for (int o = 16; o > 0; o >>= 1) {
            vA = max(vA, __shfl_down_sync(FULL, vA, o));
            vB = max(vB, __shfl_down_sync(FULL, vB, o));
        }
        if (lane == 0) { s_redA[w] = vA; s_redB[w] = vB; }
        __syncthreads();
        if (t == 0) {
            int mA = s_redA[0], mB = s_redB[0];
            #pragma unroll
            for (int k = 1; k < NWARP; k++) {
                mA = max(mA, s_redA[k]);
                mB = max(mB, s_redB[k]);
            }
            atomicMax(&g_hmax[pr],     (unsigned)mA);
            atomicMax(&g_hmax[pr + 8], (unsigned)mB);
        }
    }

    // ------- completion: LAST-arriving block finalizes ----------------------
    __syncthreads();
    if (t == 0) {
        __threadfence();
        s_old = atomicAdd(&g_done, 1u);
    }
    __syncthreads();
    if (((s_old + 1u) % NBLK) != 0u) return;

    if (t < 32) {
        float term = 0.0f;
        unsigned h2u = 0u;
        int aA = 0, aB = 0;
        if (t < NB) {
            h2u = max(g_hmax[t], g_hmax[t + 8]);
            #pragma unroll
            for (int k = 0; k < 16; k++) {
                aA |= g_anyp[t][k];
                aB |= g_anyp[t + 8][k];
            }
        }
        __syncwarp();
        if (t < NIMG) g_hmax[t] = 0u;        // reset for next replay
        if (t < NB) {
            bool empty = !(aA && aB);
            float hd = sqrtf((float)h2u);
            term = empty ? 1.0f : (1.0f - 1.0f / (1.0f + hd));
        }
        #pragma unroll
        for (int o = 16; o > 0; o >>= 1)
            term += __shfl_down_sync(FULL, term, o);
        if (t == 0) out[0] = term / (float)NB;
    }
}

extern "C" void kernel_launch(void* const* d_in, const int* in_sizes, int n_in,
                              void* d_out, int out_size) {
    const float* inputs  = (const float*)d_in[0];
    const float* targets = (const float*)d_in[1];
    float* out = (float*)d_out;
    hausdorff_fused<<<NBLK, NTHR>>>(inputs, targets, out);
}